// round 1
// baseline (speedup 1.0000x reference)
#include <cuda_runtime.h>
#include <math.h>

// Problem constants
#define B_   16
#define C_   512
#define NH_  8
#define HD_  64
#define N_   1024          // H*W = 32*32
#define QSCALE 0.125f      // HD^-0.5

// Scratch (device globals: allocation-free rule)
__device__ float g_qkv[(size_t)3 * B_ * C_ * N_];   // [s][b][c][n], c = h*64+d  (~100 MB)
__device__ float g_attn[(size_t)B_ * C_ * N_];      // [b][c][n]                (~33 MB)

// ---------------------------------------------------------------------------
// GEMM: out[b][o][n] = sum_c W[o][c] * X[b][c][n]   (per-batch, X n-contiguous)
// BM=64 (o), BN=64 (n), BK=16, 256 threads, 4x4 register micro-tile.
// MODE 0: scatter to g_qkv (scale Q);  MODE 1: read g_attn, add bias, write out.
// ---------------------------------------------------------------------------
template<int MODE>
__global__ __launch_bounds__(256)
void gemm_kernel(const float* __restrict__ W, const float* __restrict__ Xin,
                 const float* __restrict__ bias, float* __restrict__ out)
{
    const int b  = blockIdx.z;
    const int o0 = blockIdx.x * 64;
    const int n0 = blockIdx.y * 64;
    const int tid = threadIdx.x;
    const int tx = tid & 15, ty = tid >> 4;

    __shared__ float Ws[16][64];   // [k][m]
    __shared__ float Xs[16][64];   // [k][j]

    const float* Xb = (MODE == 1 ? g_attn : Xin) + (size_t)b * C_ * N_;

    float acc[4][4];
    #pragma unroll
    for (int i = 0; i < 4; i++)
        #pragma unroll
        for (int j = 0; j < 4; j++) acc[i][j] = 0.f;

    for (int kt = 0; kt < C_; kt += 16) {
        #pragma unroll
        for (int r = 0; r < 4; r++) {
            int idx = tid + r * 256;          // 0..1023
            int m = idx >> 4, k = idx & 15;
            Ws[k][m] = W[(size_t)(o0 + m) * C_ + kt + k];
        }
        #pragma unroll
        for (int r = 0; r < 4; r++) {
            int idx = tid + r * 256;
            int k = idx >> 6, j = idx & 63;
            Xs[k][j] = Xb[(size_t)(kt + k) * N_ + n0 + j];
        }
        __syncthreads();

        #pragma unroll
        for (int k = 0; k < 16; k++) {
            float4 a4 = *(const float4*)&Ws[k][ty * 4];
            float4 x4 = *(const float4*)&Xs[k][tx * 4];
            float av[4] = {a4.x, a4.y, a4.z, a4.w};
            float xv[4] = {x4.x, x4.y, x4.z, x4.w};
            #pragma unroll
            for (int i = 0; i < 4; i++)
                #pragma unroll
                for (int j = 0; j < 4; j++)
                    acc[i][j] += av[i] * xv[j];
        }
        __syncthreads();
    }

    #pragma unroll
    for (int i = 0; i < 4; i++) {
        int o = o0 + ty * 4 + i;
        #pragma unroll
        for (int j = 0; j < 4; j++) {
            int n = n0 + tx * 4 + j;
            float v = acc[i][j];
            if (MODE == 0) {
                int s   = o >> 9;      // 0=q,1=k,2=v
                int rem = o & 511;     // h*64+d
                if (s == 0) v *= QSCALE;
                g_qkv[(((size_t)s * B_ + b) * C_ + rem) * N_ + n] = v;
            } else {
                out[((size_t)b * C_ + o) * N_ + n] = v + bias[o];
            }
        }
    }
}

// ---------------------------------------------------------------------------
// Flash attention: 1 thread = 1 query row. q[64], o[64] in regs.
// K/V tiles (64 keys) in smem, (d, j) layout -> LDS.128 broadcast, 4 FMA/LDS.
// Lazy online softmax: rescale o only when the running max increases.
// Grid: (B*NH, N/128), 128 threads.
// ---------------------------------------------------------------------------
__global__ __launch_bounds__(128)
void attn_kernel()
{
    const int bh = blockIdx.x;
    const int b  = bh >> 3, h = bh & 7;
    const int tid = threadIdx.x;
    const int n  = blockIdx.y * 128 + tid;

    __shared__ float Ks[64 * 64];   // [d][j]
    __shared__ float Vs[64 * 64];   // [d][j]

    const size_t headoff = ((size_t)b * C_ + h * HD_) * N_;
    const float* Qg = g_qkv + headoff;                               // s=0 (pre-scaled)
    const float* Kg = g_qkv + (size_t)1 * B_ * C_ * N_ + headoff;    // s=1
    const float* Vg = g_qkv + (size_t)2 * B_ * C_ * N_ + headoff;    // s=2

    float q[64], o[64];
    #pragma unroll
    for (int d = 0; d < 64; d++) { q[d] = Qg[(size_t)d * N_ + n]; o[d] = 0.f; }

    float m = -INFINITY, l = 0.f;

    for (int t0 = 0; t0 < N_; t0 += 64) {
        // cooperative tile load: coalesced float4 over n, conflict-free stores
        for (int f = tid; f < 64 * 16; f += 128) {
            int d = f >> 4, j4 = (f & 15) * 4;
            *(float4*)&Ks[d * 64 + j4] = *(const float4*)&Kg[(size_t)d * N_ + t0 + j4];
            *(float4*)&Vs[d * 64 + j4] = *(const float4*)&Vg[(size_t)d * N_ + t0 + j4];
        }
        __syncthreads();

        for (int j4 = 0; j4 < 64; j4 += 4) {
            float s0 = 0.f, s1 = 0.f, s2 = 0.f, s3 = 0.f;
            #pragma unroll
            for (int d = 0; d < 64; d++) {
                float4 kk = *(const float4*)&Ks[d * 64 + j4];
                s0 += q[d] * kk.x; s1 += q[d] * kk.y;
                s2 += q[d] * kk.z; s3 += q[d] * kk.w;
            }
            float gm = fmaxf(fmaxf(s0, s1), fmaxf(s2, s3));
            if (gm > m) {
                float corr = __expf(m - gm);   // exp(-inf)=0 handles first tile
                l *= corr;
                #pragma unroll
                for (int d = 0; d < 64; d++) o[d] *= corr;
                m = gm;
            }
            float p0 = __expf(s0 - m), p1 = __expf(s1 - m);
            float p2 = __expf(s2 - m), p3 = __expf(s3 - m);
            l += p0 + p1 + p2 + p3;
            #pragma unroll
            for (int d = 0; d < 64; d++) {
                float4 vv = *(const float4*)&Vs[d * 64 + j4];
                o[d] += p0 * vv.x + p1 * vv.y + p2 * vv.z + p3 * vv.w;
            }
        }
        __syncthreads();
    }

    const float inv = 1.f / l;
    float* Og = g_attn + headoff;
    #pragma unroll
    for (int d = 0; d < 64; d++)
        Og[(size_t)d * N_ + n] = o[d] * inv;   // coalesced across threads per d
}

// ---------------------------------------------------------------------------
extern "C" void kernel_launch(void* const* d_in, const int* in_sizes, int n_in,
                              void* d_out, int out_size)
{
    const float* x      = (const float*)d_in[0];   // [B, C, H, W]
    const float* w_qkv  = (const float*)d_in[1];   // [3C, C]
    const float* w_proj = (const float*)d_in[2];   // [C, C]
    const float* b_proj = (const float*)d_in[3];   // [C]
    float* out = (float*)d_out;                    // [B, C, H, W]

    dim3 g1(3 * C_ / 64, N_ / 64, B_);   // 24 x 16 x 16
    gemm_kernel<0><<<g1, 256>>>(w_qkv, x, nullptr, nullptr);

    attn_kernel<<<dim3(B_ * NH_, N_ / 128), 128>>>();

    dim3 g3(C_ / 64, N_ / 64, B_);       // 8 x 16 x 16
    gemm_kernel<1><<<g3, 256>>>(w_proj, nullptr, b_proj, out);
}